// round 17
// baseline (speedup 1.0000x reference)
#include <cuda_runtime.h>
#include <cuda_bf16.h>
#include <math.h>
#include <stdint.h>

#define Bv 4
#define Tv 4096
#define Cv 512
#define Rv (Bv*Tv)            // 16384 rows
#define Fv (4*Cv)             // 2048
#define GUARDE (2048*Cv)      // guard rows (zero-init) for shifted scan operand
#define Sm ((long)Cv*Cv)

typedef __nv_bfloat16 bf16;

// ---------------- static device scratch (zero-initialized) ----------------
__device__ bf16 g_qH[GUARDE + Rv*Cv];
__device__ bf16 g_qL[GUARDE + Rv*Cv];
__device__ bf16 g_vH[Rv*Cv], g_vL[Rv*Cv];
__device__ float g_z[Rv*Cv];
__device__ bf16 g_hH[Rv*Cv], g_hL[Rv*Cv];
__device__ bf16 g_fcH[Rv*Fv], g_fcL[Rv*Fv];
// weight splits
__device__ bf16 g_WqH[Cv*Cv], g_WqL[Cv*Cv];
__device__ bf16 g_WvH[Cv*Cv], g_WvL[Cv*Cv];
__device__ bf16 g_WoH[Cv*Cv], g_WoL[Cv*Cv];
__device__ bf16 g_WfcH[Fv*Cv], g_WfcL[Fv*Cv];
__device__ bf16 g_WprH[Cv*Fv], g_WprL[Cv*Fv];
// polar scratch (x2 matrices, batched)
__device__ bf16 g_XaH[2*Cv*Cv], g_XaL[2*Cv*Cv];
__device__ bf16 g_XbH[2*Cv*Cv], g_XbL[2*Cv*Cv];
__device__ bf16 g_XtH[2*Cv*Cv], g_XtL[2*Cv*Cv];
__device__ bf16 g_YH [2*Cv*Cv], g_YL [2*Cv*Cv];
__device__ bf16 g_MH [2*Cv*Cv], g_ML [2*Cv*Cv];
__device__ float g_YF[2*Cv*Cv];
__device__ bf16 g_PcH[Cv*2*Cv], g_PcL[Cv*2*Cv];   // [P1||P2] along K (512 x 1024)
__device__ float g_part[2*Cv];
__device__ float g_rn[2];
// software grid barrier state (zero-init; count returns to 0 after each barrier)
__device__ int g_barC;
__device__ volatile int g_barGen;

// ================= helpers =================
__device__ __forceinline__ uint32_t smem_to_u32(const void* p) {
    uint32_t a;
    asm("{ .reg .u64 t; cvta.to.shared.u64 t, %1; cvt.u32.u64 %0, t; }" : "=r"(a) : "l"(p));
    return a;
}
__device__ __forceinline__ void split2(float x, bf16& h, bf16& l) {
    h = __float2bfloat16(x);
    l = __float2bfloat16(x - __bfloat162float(h));
}
__device__ __forceinline__ uint32_t pk2(bf16 a, bf16 b) {
    __nv_bfloat162 t; t.x = a; t.y = b;
    return *(uint32_t*)&t;
}
__device__ __forceinline__ void up2(uint32_t u, float& a, float& b) {
    __nv_bfloat162 t = *(__nv_bfloat162*)&u;
    a = __bfloat162float(t.x); b = __bfloat162float(t.y);
}
__device__ __forceinline__ void ldsm4(uint32_t (&r)[4], uint32_t addr) {
    asm volatile("ldmatrix.sync.aligned.m8n8.x4.shared.b16 {%0,%1,%2,%3}, [%4];"
        : "=r"(r[0]), "=r"(r[1]), "=r"(r[2]), "=r"(r[3]) : "r"(addr));
}
__device__ __forceinline__ void mma16816(float (&d)[4], const uint32_t (&a)[4],
                                         uint32_t b0, uint32_t b1) {
    asm volatile("mma.sync.aligned.m16n8k16.row.col.f32.bf16.bf16.f32 "
        "{%0,%1,%2,%3}, {%4,%5,%6,%7}, {%8,%9}, {%0,%1,%2,%3};"
        : "+f"(d[0]), "+f"(d[1]), "+f"(d[2]), "+f"(d[3])
        : "r"(a[0]), "r"(a[1]), "r"(a[2]), "r"(a[3]), "r"(b0), "r"(b1));
}
__device__ __forceinline__ void cp_async16(uint32_t so, const void* gp) {
    asm volatile("cp.async.cg.shared.global [%0], [%1], 16;" :: "r"(so), "l"(gp) : "memory");
}
#define CP_COMMIT() asm volatile("cp.async.commit_group;" ::: "memory")
#define CP_WAIT(n)  asm volatile("cp.async.wait_group %0;" :: "n"(n) : "memory")

// all-128-CTA grid barrier (all CTAs co-resident: 128 <= 148 SMs)
__device__ __forceinline__ void gridbar() {
    __syncthreads();
    if (threadIdx.x == 0) {
        int gen = g_barGen;
        __threadfence();
        if (atomicAdd(&g_barC, 1) == 127) {
            g_barC = 0;
            __threadfence();
            g_barGen = gen + 1;
        } else {
            while (g_barGen == gen) { __nanosleep(64); }
        }
    }
    __syncthreads();
}

// ================= mma.sync split-bf16 GEMM: C = alpha*A@B^T (+beta*add +diag*I) =====
// (big-GEMM path; 128x128 @ OCC=2 / 3-stage is the measured optimum)
struct GA {
    const bf16 *Ah, *Al, *Ah2, *Al2, *Bh, *Bl;
    int M, N, K, K1, lda, ldb, mskip;
    long zA, zB;
};
struct TEpi {
    float alpha, beta, diag;
    const float* add; long zAdd;
    int gelu;
    float* outF; bf16 *outH, *outL; long zOut;
};

template<int BM, int BN, int WR, int OCC, int NSTG>
__global__ __launch_bounds__(256, OCC)
void mma_gemm(GA g, TEpi e)
{
    constexpr int WC = 8/WR;
    constexpr int MF = BM/(16*WR);
    constexpr int NF = (BN/WC)/8;
    constexpr int NB = NF/2;
    static_assert(MF >= 1 && NB >= 1, "tile too small");
    constexpr int ASZA = BM*64;
    constexpr int ASZB = BN*64;
    constexpr int BUF = 2*ASZA + 2*ASZB;
    extern __shared__ char smem[];
    const uint32_t sb = smem_to_u32(smem);
    const int tid  = threadIdx.x;
    const int lane = tid & 31;
    const int wid  = tid >> 5;
    const int wm   = wid % WR;
    const int wn   = wid / WR;
    const int m0 = g.mskip + blockIdx.y * BM;
    const int n0 = blockIdx.x * BN;
    const int bz = blockIdx.z;
    const int NC = g.K / 32;

    const bf16 *Ah = g.Ah + bz*g.zA,  *Al = g.Al + bz*g.zA;
    const bf16 *Ah2 = g.Ah2 + bz*g.zA, *Al2 = g.Al2 + bz*g.zA;
    const bf16 *Bh = g.Bh + bz*g.zB,  *Bl = g.Bl + bz*g.zB;

    int aOff[2][MF], bOff[2][NB];
    {
        const int aKb = (lane >> 4) * 16;
#pragma unroll
        for (int mf = 0; mf < MF; mf++) {
            int r = wm * (BM/WR) + mf * 16 + (lane & 15);
            int base = (r >> 1) * 128, po = (r & 1) * 64, xm = ((r >> 1) & 7) << 4;
#pragma unroll
            for (int ks = 0; ks < 2; ks++)
                aOff[ks][mf] = base + ((po + ks * 32 + aKb) ^ xm);
        }
        const int bKb = ((lane >> 3) & 1) * 16;
#pragma unroll
        for (int nb = 0; nb < NB; nb++) {
            int r = wn * (BN/WC) + nb * 16 + ((lane >> 4) << 3) + (lane & 7);
            int base = (r >> 1) * 128, po = (r & 1) * 64, xm = ((r >> 1) & 7) << 4;
#pragma unroll
            for (int ks = 0; ks < 2; ks++)
                bOff[ks][nb] = base + ((po + ks * 32 + bKb) ^ xm);
        }
    }

    float acc[MF][NF][4];
#pragma unroll
    for (int i = 0; i < MF; i++)
#pragma unroll
        for (int j = 0; j < NF; j++)
#pragma unroll
            for (int t = 0; t < 4; t++) acc[i][j][t] = 0.f;

    auto loadChunk = [&](int c) {
        const long cofs = (long)c * 32;
        const int st = c % NSTG;
        const bf16* AHc = Ah; const bf16* ALc = Al;
        long acol = cofs;
        if (cofs >= g.K1) { AHc = Ah2; ALc = Al2; acol = cofs - g.K1; }
        constexpr int TVA = BM * 4;
        constexpr int TVB = BN * 4;
        constexpr int NVEC = 2*TVA + 2*TVB;
#pragma unroll
        for (int t = 0; t < NVEC/256; t++) {
            int u = tid + t * 256;
            const bf16* base;
            int row, seg, sofs;
            if (u < TVA)            { base = AHc; row = u >> 2;          seg = u & 3;        sofs = 0;           }
            else if (u < 2*TVA)     { base = ALc; row = (u-TVA) >> 2;    seg = (u-TVA) & 3;  sofs = ASZA;        }
            else if (u < 2*TVA+TVB) { base = Bh;  row = (u-2*TVA) >> 2;  seg = (u-2*TVA) & 3; sofs = 2*ASZA;     }
            else                    { base = Bl;  row = (u-2*TVA-TVB) >> 2; seg = (u-2*TVA-TVB) & 3; sofs = 2*ASZA+ASZB; }
            const bf16* gp;
            if (sofs < 2*ASZA) gp = base + (long)(m0 + row) * g.lda + acol;
            else               gp = base + (long)(n0 + row) * g.ldb + cofs;
            gp += seg * 8;
            int j = row >> 1, p = row & 1;
            uint32_t so = sb + st * BUF + sofs + j * 128
                        + ((p * 64 + seg * 16) ^ ((j & 7) << 4));
            cp_async16(so, gp);
        }
        CP_COMMIT();
    };

    for (int i = 0; i < NSTG - 1 && i < NC; i++) loadChunk(i);

    for (int c = 0; c < NC; c++) {
        int rem = NC - 1 - c;
        if (rem > NSTG - 2) rem = NSTG - 2;
        if (rem >= 1) CP_WAIT(1);
        else          CP_WAIT(0);
        __syncthreads();
        if (c + NSTG - 1 < NC) loadChunk(c + NSTG - 1);

        const uint32_t bufB = sb + (c % NSTG) * BUF;
#pragma unroll
        for (int ks = 0; ks < 2; ks++) {
            uint32_t afH[MF][4], bfH[NB][4];
#pragma unroll
            for (int mf = 0; mf < MF; mf++)
                ldsm4(afH[mf], bufB + aOff[ks][mf]);
#pragma unroll
            for (int nb = 0; nb < NB; nb++)
                ldsm4(bfH[nb], bufB + 2*ASZA + bOff[ks][nb]);
#pragma unroll
            for (int mf = 0; mf < MF; mf++)
#pragma unroll
                for (int nf = 0; nf < NF; nf++)
                    mma16816(acc[mf][nf], afH[mf], bfH[nf>>1][(nf&1)*2], bfH[nf>>1][(nf&1)*2+1]);
            {
                uint32_t afL[MF][4];
#pragma unroll
                for (int mf = 0; mf < MF; mf++)
                    ldsm4(afL[mf], bufB + ASZA + aOff[ks][mf]);
#pragma unroll
                for (int mf = 0; mf < MF; mf++)
#pragma unroll
                    for (int nf = 0; nf < NF; nf++)
                        mma16816(acc[mf][nf], afL[mf], bfH[nf>>1][(nf&1)*2], bfH[nf>>1][(nf&1)*2+1]);
            }
            {
                uint32_t bfL[NB][4];
#pragma unroll
                for (int nb = 0; nb < NB; nb++)
                    ldsm4(bfL[nb], bufB + 2*ASZA + ASZB + bOff[ks][nb]);
#pragma unroll
                for (int mf = 0; mf < MF; mf++)
#pragma unroll
                    for (int nf = 0; nf < NF; nf++)
                        mma16816(acc[mf][nf], afH[mf], bfL[nf>>1][(nf&1)*2], bfL[nf>>1][(nf&1)*2+1]);
            }
        }
    }
    __syncthreads();

    // ---- epilogue ----
    float* outF = e.outF ? e.outF + bz*e.zOut : (float*)0;
    bf16*  outH = e.outH ? e.outH + bz*e.zOut : (bf16*)0;
    bf16*  outL = e.outL ? e.outL + bz*e.zOut : (bf16*)0;
    const float* add = e.add ? e.add + bz*e.zAdd : (const float*)0;
    const int rl = lane >> 2;
    const int cl = (lane & 3) * 2;
#pragma unroll
    for (int mf = 0; mf < MF; mf++) {
#pragma unroll
        for (int nf = 0; nf < NF; nf++) {
            int lc = wn * (BN/WC) + nf * 8 + cl;
            int c0 = n0 + lc;
#pragma unroll
            for (int half = 0; half < 2; half++) {
                int lr = wm * (BM/WR) + mf * 16 + rl + half * 8;
                int row = m0 + lr;
                long ofs = (long)row * g.N + c0;
                float f0 = e.alpha * acc[mf][nf][half*2];
                float f1 = e.alpha * acc[mf][nf][half*2 + 1];
                if (add) {
                    float2 ra = *(const float2*)(add + ofs);
                    f0 += e.beta * ra.x; f1 += e.beta * ra.y;
                }
                if (e.diag != 0.f) {
                    if (row == c0)     f0 += e.diag;
                    if (row == c0 + 1) f1 += e.diag;
                }
                if (e.gelu) {
                    f0 = 0.5f * f0 * (1.f + erff(f0 * 0.70710678118654752f));
                    f1 = 0.5f * f1 * (1.f + erff(f1 * 0.70710678118654752f));
                }
                if (outF)
                    *(float2*)(outF + ofs) = make_float2(f0, f1);
                if (outH) {
                    bf16 h0, h1, l0, l1;
                    split2(f0, h0, l0);
                    split2(f1, h1, l1);
                    *(uint32_t*)(outH + ofs) = pk2(h0, h1);
                    *(uint32_t*)(outL + ofs) = pk2(l0, l1);
                }
            }
        }
    }
}

// ================= persistent polar chain (35 fused GEMM phases, 64x64 tiles) =====
struct PArg {
    const bf16 *Ah, *Al, *Bh, *Bl;   // operands (pre-offset by mat), pitch Cv, [*,K=512]
    float alpha, beta, diag;
    const float* add;                // pitch Cv
    float* outF;                     // pitch Cv
    bf16 *outH, *outL; int ldo;      // pitch ldo
    bf16 *outTH, *outTL;             // transposed out, pitch Cv
};

// one 64x64 tile, K=512, 3-stage cp.async; 8 warps (2x4): 32 rows x 16 cols each
__device__ void pgemm(char* smem, int m0, int n0, const PArg& p)
{
    constexpr int ASZ = 4096;                 // one operand tile: 64 rows x 64B
    constexpr int BUF = 4*ASZ;                // 16KB/stage
    const uint32_t sb = smem_to_u32(smem);
    const int tid = threadIdx.x, lane = tid & 31, wid = tid >> 5;
    const int wm = wid & 1, wn = wid >> 1;
    const int NC = 16;

    int aOff[2][2], bOff[2];
    {
        const int aKb = (lane >> 4) * 16;
#pragma unroll
        for (int mf = 0; mf < 2; mf++) {
            int r = wm*32 + mf*16 + (lane & 15);
            int base = (r>>1)*128, po = (r&1)*64, xm = ((r>>1)&7)<<4;
            aOff[0][mf] = base + ((po + aKb) ^ xm);
            aOff[1][mf] = base + ((po + 32 + aKb) ^ xm);
        }
        const int bKb = ((lane >> 3) & 1) * 16;
        int r = wn*16 + ((lane >> 4) << 3) + (lane & 7);
        int base = (r>>1)*128, po = (r&1)*64, xm = ((r>>1)&7)<<4;
        bOff[0] = base + ((po + bKb) ^ xm);
        bOff[1] = base + ((po + 32 + bKb) ^ xm);
    }

    float acc[2][2][4];
#pragma unroll
    for (int i = 0; i < 2; i++)
#pragma unroll
        for (int j = 0; j < 2; j++)
#pragma unroll
            for (int t = 0; t < 4; t++) acc[i][j][t] = 0.f;

    auto loadChunk = [&](int c) {
        const long cofs = (long)c * 32;
        const int st = c % 3;
#pragma unroll
        for (int t = 0; t < 4; t++) {
            int u = tid + t * 256;
            const bf16* base; int w, sofs;
            if (u < 256)      { base = p.Ah; w = u;       sofs = 0; }
            else if (u < 512) { base = p.Al; w = u - 256; sofs = ASZ; }
            else if (u < 768) { base = p.Bh; w = u - 512; sofs = 2*ASZ; }
            else              { base = p.Bl; w = u - 768; sofs = 3*ASZ; }
            int row = w >> 2, seg = w & 3;
            const bf16* gp = (sofs < 2*ASZ) ? base + (long)(m0 + row) * Cv + cofs
                                            : base + (long)(n0 + row) * Cv + cofs;
            gp += seg * 8;
            int j = row >> 1, pp = row & 1;
            uint32_t so = sb + st * BUF + sofs + j * 128
                        + ((pp * 64 + seg * 16) ^ ((j & 7) << 4));
            cp_async16(so, gp);
        }
        CP_COMMIT();
    };

    loadChunk(0);
    loadChunk(1);
    for (int c = 0; c < NC; c++) {
        if (c + 1 < NC) CP_WAIT(1); else CP_WAIT(0);
        __syncthreads();
        if (c + 2 < NC) loadChunk(c + 2);
        const uint32_t bufB = sb + (c % 3) * BUF;
#pragma unroll
        for (int ks = 0; ks < 2; ks++) {
            uint32_t afH[2][4], bfH[4];
            ldsm4(afH[0], bufB + aOff[ks][0]);
            ldsm4(afH[1], bufB + aOff[ks][1]);
            ldsm4(bfH, bufB + 2*ASZ + bOff[ks]);
#pragma unroll
            for (int mf = 0; mf < 2; mf++) {
                mma16816(acc[mf][0], afH[mf], bfH[0], bfH[1]);
                mma16816(acc[mf][1], afH[mf], bfH[2], bfH[3]);
            }
            {
                uint32_t afL[2][4];
                ldsm4(afL[0], bufB + ASZ + aOff[ks][0]);
                ldsm4(afL[1], bufB + ASZ + aOff[ks][1]);
#pragma unroll
                for (int mf = 0; mf < 2; mf++) {
                    mma16816(acc[mf][0], afL[mf], bfH[0], bfH[1]);
                    mma16816(acc[mf][1], afL[mf], bfH[2], bfH[3]);
                }
            }
            {
                uint32_t bfL[4];
                ldsm4(bfL, bufB + 3*ASZ + bOff[ks]);
#pragma unroll
                for (int mf = 0; mf < 2; mf++) {
                    mma16816(acc[mf][0], afH[mf], bfL[0], bfL[1]);
                    mma16816(acc[mf][1], afH[mf], bfL[2], bfL[3]);
                }
            }
        }
    }
    __syncthreads();

    // epilogue (smem reused for transpose staging: 64 x 65 bf16 x2 = 16.6KB)
    bf16* sH = (bf16*)smem;
    bf16* sL = sH + 64*65;
    const int rl = lane >> 2, cl = (lane & 3) * 2;
#pragma unroll
    for (int mf = 0; mf < 2; mf++) {
#pragma unroll
        for (int nf = 0; nf < 2; nf++) {
            int lc = wn*16 + nf*8 + cl;
            int c0 = n0 + lc;
#pragma unroll
            for (int half = 0; half < 2; half++) {
                int lr = wm*32 + mf*16 + rl + half*8;
                int row = m0 + lr;
                float f0 = p.alpha * acc[mf][nf][half*2];
                float f1 = p.alpha * acc[mf][nf][half*2 + 1];
                if (p.add) {
                    float2 ra = *(const float2*)(p.add + (long)row*Cv + c0);
                    f0 += p.beta * ra.x; f1 += p.beta * ra.y;
                }
                if (p.diag != 0.f) {
                    if (row == c0)     f0 += p.diag;
                    if (row == c0 + 1) f1 += p.diag;
                }
                if (p.outF)
                    *(float2*)(p.outF + (long)row*Cv + c0) = make_float2(f0, f1);
                bf16 h0, h1, l0, l1;
                split2(f0, h0, l0);
                split2(f1, h1, l1);
                if (p.outH) {
                    long ofs = (long)row * p.ldo + c0;
                    *(uint32_t*)(p.outH + ofs) = pk2(h0, h1);
                    *(uint32_t*)(p.outL + ofs) = pk2(l0, l1);
                }
                if (p.outTH) {
                    sH[lr*65 + lc] = h0; sH[lr*65 + lc + 1] = h1;
                    sL[lr*65 + lc] = l0; sL[lr*65 + lc + 1] = l1;
                }
            }
        }
    }
    if (p.outTH) {
        __syncthreads();
#pragma unroll
        for (int it = 0; it < 16; it++) {
            int idx = tid + it * 256;
            int j = idx >> 6;   // col 0..63
            int i = idx & 63;   // row 0..63
            long o = (long)(n0 + j) * Cv + m0 + i;
            p.outTH[o] = sH[i*65 + j];
            p.outTL[o] = sL[i*65 + j];
        }
    }
}

__global__ __launch_bounds__(256, 2)
void polar_chain(bf16* XaH0, bf16* XaL0, bf16* XbH0, bf16* XbL0,
                 bf16* XtH, bf16* XtL, bf16* YH, bf16* YL,
                 bf16* MH, bf16* ML, float* YF, bf16* PcH, bf16* PcL)
{
    __shared__ char smem[49152];
    const int cid = blockIdx.x;          // 128 CTAs: 2 mats x (8 x 8) 64x64 tiles
    const int mat = cid >> 6;
    const int m0 = ((cid >> 3) & 7) * 64;
    const int n0 = (cid & 7) * 64;
    const long mo = (long)mat * Sm;
    bf16 *aH = XaH0 + mo, *aL = XaL0 + mo, *bH = XbH0 + mo, *bL = XbL0 + mo;
    bf16 *tH = XtH + mo, *tL = XtL + mo;
    bf16 *yH = YH + mo, *yL = YL + mo, *mH = MH + mo, *mL = ML + mo;
    float* yF = YF + mo;

    for (int it = 0; it < 9; it++) {
        // Y = Xt @ Xt^T (= X^T X)
        { PArg p{tH,tL,tH,tL, 1.f,0.f,0.f, 0, yF, yH,yL,Cv, 0,0}; pgemm(smem,m0,n0,p); }
        gridbar();
        // M = 2.0315*Y@Y^T - 4.7750*Y + 3.4445*I
        { PArg p{yH,yL,yH,yL, 2.0315f,-4.7750f,3.4445f, yF, 0, mH,mL,Cv, 0,0}; pgemm(smem,m0,n0,p); }
        gridbar();
        // X' = X @ M^T; also emit Xt'
        { PArg p{aH,aL,mH,mL, 1.f,0.f,0.f, 0, 0, bH,bL,Cv, tH,tL}; pgemm(smem,m0,n0,p); }
        gridbar();
        bf16* t;
        t = aH; aH = bH; bH = t;
        t = aL; aL = bL; bL = t;
    }
    for (int it = 0; it < 4; it++) {
        // G = -0.5*Xt@Xt^T + 1.5I
        { PArg p{tH,tL,tH,tL, -0.5f,0.f,1.5f, 0, 0, mH,mL,Cv, 0,0}; pgemm(smem,m0,n0,p); }
        gridbar();
        if (it < 3) {
            { PArg p{aH,aL,mH,mL, 1.f,0.f,0.f, 0, 0, bH,bL,Cv, tH,tL}; pgemm(smem,m0,n0,p); }
            gridbar();
            bf16* t;
            t = aH; aH = bH; bH = t;
            t = aL; aL = bL; bL = t;
        } else {
            // last X-step writes straight into Pc ([P1||P2] along K: pitch 1024)
            PArg p{aH,aL,mH,mL, 1.f,0.f,0.f, 0, 0, PcH + mat*Cv, PcL + mat*Cv, 2*Cv, 0,0};
            pgemm(smem,m0,n0,p);
        }
    }
}

// ---------------- elementwise / reduction kernels ----------------
__global__ void ln_kernel(const float* __restrict__ x, const float* __restrict__ w,
                          bf16* __restrict__ oh, bf16* __restrict__ ol)
{
    const int r = blockIdx.x, tid = threadIdx.x;
    float4 f = ((const float4*)(x + (long)r*Cv))[tid];
    float s = f.x+f.y+f.z+f.w;
    float q = f.x*f.x+f.y*f.y+f.z*f.z+f.w*f.w;
    __shared__ float shs[4], shq[4];
#pragma unroll
    for (int off=16; off>0; off>>=1) {
        s += __shfl_down_sync(0xffffffffu, s, off);
        q += __shfl_down_sync(0xffffffffu, q, off);
    }
    if ((tid&31)==0) { shs[tid>>5]=s; shq[tid>>5]=q; }
    __syncthreads();
    float S = shs[0]+shs[1]+shs[2]+shs[3];
    float Q = shq[0]+shq[1]+shq[2]+shq[3];
    float mean = S*(1.f/Cv);
    float var  = Q*(1.f/Cv) - mean*mean;
    float inv  = rsqrtf(var + 1e-5f);
    float4 wf = ((const float4*)w)[tid];
    float o0=(f.x-mean)*inv*wf.x, o1=(f.y-mean)*inv*wf.y;
    float o2=(f.z-mean)*inv*wf.z, o3=(f.w-mean)*inv*wf.w;
    bf16 h0,h1,h2,h3,l0,l1,l2,l3;
    split2(o0,h0,l0); split2(o1,h1,l1); split2(o2,h2,l2); split2(o3,h3,l3);
    long ofs = (long)r*Cv + tid*4;
    uint2 uh; uh.x=pk2(h0,h1); uh.y=pk2(h2,h3);
    uint2 ul; ul.x=pk2(l0,l1); ul.y=pk2(l2,l3);
    *(uint2*)(oh+ofs)=uh; *(uint2*)(ol+ofs)=ul;
}

// in-place scan combine: q[t] <- rms(z[t]) for t >= d; 4 rows per 512-thr block.
__global__ void pscan_combine(const float* __restrict__ z,
                              bf16* __restrict__ qH, bf16* __restrict__ qL,
                              int d, int mskip)
{
    const int grp = threadIdx.x >> 7;
    const int tid = threadIdx.x & 127;
    const int t = mskip + blockIdx.x * 4 + grp;
    const bool active = (t >= d);
    const int r = blockIdx.y * Tv + t;
    long ofs = (long)r*Cv + tid*4;
    float4 f = *(const float4*)(z+ofs);
    float q = f.x*f.x+f.y*f.y+f.z*f.z+f.w*f.w;
    __shared__ float shq[4][4];
#pragma unroll
    for (int off=16; off>0; off>>=1) q += __shfl_down_sync(0xffffffffu, q, off);
    if ((tid&31)==0) shq[grp][tid>>5]=q;
    __syncthreads();
    float Q = shq[grp][0]+shq[grp][1]+shq[grp][2]+shq[grp][3];
    float sc = rsqrtf(Q*(1.f/Cv) + 1e-6f);
    if (!active) return;
    float o0=f.x*sc, o1=f.y*sc, o2=f.z*sc, o3=f.w*sc;
    bf16 h0,h1,h2,h3,l0,l1,l2,l3;
    split2(o0,h0,l0); split2(o1,h1,l1); split2(o2,h2,l2); split2(o3,h3,l3);
    uint2 uh; uh.x=pk2(h0,h1); uh.y=pk2(h2,h3);
    uint2 ul; ul.x=pk2(l0,l1); ul.y=pk2(l2,l3);
    *(uint2*)(qH+ofs)=uh; *(uint2*)(qL+ofs)=ul;
}

__global__ void mul_split(const bf16* __restrict__ qH, const bf16* __restrict__ qL,
                          const bf16* __restrict__ vH, const bf16* __restrict__ vL,
                          bf16* __restrict__ H, bf16* __restrict__ L)
{
    long i = ((long)blockIdx.x*256 + threadIdx.x)*4;
    uint2 a = *(const uint2*)(qH+i), b = *(const uint2*)(qL+i);
    uint2 c = *(const uint2*)(vH+i), d = *(const uint2*)(vL+i);
    float q0,q1,q2,q3,ql0,ql1,ql2,ql3,v0,v1,v2,v3,vl0,vl1,vl2,vl3;
    up2(a.x,q0,q1); up2(a.y,q2,q3); up2(b.x,ql0,ql1); up2(b.y,ql2,ql3);
    up2(c.x,v0,v1); up2(c.y,v2,v3); up2(d.x,vl0,vl1); up2(d.y,vl2,vl3);
    float o0=(q0+ql0)*(v0+vl0), o1=(q1+ql1)*(v1+vl1);
    float o2=(q2+ql2)*(v2+vl2), o3=(q3+ql3)*(v3+vl3);
    bf16 h0,h1,h2,h3,l0,l1,l2,l3;
    split2(o0,h0,l0); split2(o1,h1,l1); split2(o2,h2,l2); split2(o3,h3,l3);
    uint2 uh; uh.x=pk2(h0,h1); uh.y=pk2(h2,h3);
    uint2 ul; ul.x=pk2(l0,l1); ul.y=pk2(l2,l3);
    *(uint2*)(H+i)=uh; *(uint2*)(L+i)=ul;
}

__global__ void wsplit5(const float* __restrict__ Wq, const float* __restrict__ Wv,
                        const float* __restrict__ Wo, const float* __restrict__ Wfc,
                        const float* __restrict__ Wpr,
                        bf16* WqH, bf16* WqL, bf16* WvH, bf16* WvL,
                        bf16* WoH, bf16* WoL, bf16* WfcH, bf16* WfcL,
                        bf16* WprH, bf16* WprL)
{
    const int S = Cv*Cv;
    long i = (long)blockIdx.x*256 + threadIdx.x;
    const float* W; bf16 *H, *L; long j;
    if      (i < S)       { W=Wq;  H=WqH;  L=WqL;  j=i; }
    else if (i < 2L*S)    { W=Wv;  H=WvH;  L=WvL;  j=i-S; }
    else if (i < 3L*S)    { W=Wo;  H=WoH;  L=WoL;  j=i-2L*S; }
    else if (i < 7L*S)    { W=Wfc; H=WfcH; L=WfcL; j=i-3L*S; }
    else                  { W=Wpr; H=WprH; L=WprL; j=i-7L*S; }
    float x = W[j];
    bf16 h, l; split2(x, h, l);
    H[j] = h; L[j] = l;
}

__global__ void frob1(const float* __restrict__ W1, const float* __restrict__ W2,
                      float* __restrict__ part)
{
    const int row = blockIdx.x, mat = blockIdx.y, tid = threadIdx.x;
    const float* W = mat ? W2 : W1;
    float4 f = ((const float4*)(W + (long)row*Cv))[tid];
    float q = f.x*f.x+f.y*f.y+f.z*f.z+f.w*f.w;
    __shared__ float shq[4];
#pragma unroll
    for (int off=16; off>0; off>>=1) q += __shfl_down_sync(0xffffffffu, q, off);
    if ((tid&31)==0) shq[tid>>5]=q;
    __syncthreads();
    if (tid==0) part[mat*Cv + row] = shq[0]+shq[1]+shq[2]+shq[3];
}

__global__ void frob2(const float* __restrict__ part, float* __restrict__ rn)
{
    const int mat = blockIdx.x, tid = threadIdx.x;
    __shared__ float sh[256];
    sh[tid] = part[mat*Cv + tid] + part[mat*Cv + tid + 256];
    __syncthreads();
    for (int off=128; off>0; off>>=1) {
        if (tid<off) sh[tid] += sh[tid+off];
        __syncthreads();
    }
    if (tid==0) rn[mat] = rsqrtf(sh[0]);
}

__global__ void split_tr_init(const float* __restrict__ W1, const float* __restrict__ W2,
                              const float* __restrict__ rn,
                              bf16* XH, bf16* XL, bf16* XtH, bf16* XtL)
{
    __shared__ float t[32][33];
    const int mat = blockIdx.z;
    const float* W = mat ? W2 : W1;
    const float s = rn[mat];
    const int r0 = blockIdx.y*32, c0 = blockIdx.x*32;
    const int tx = threadIdx.x, ty = threadIdx.y;
    const long mo = (long)mat*Sm;
#pragma unroll
    for (int i = 0; i < 4; i++) {
        int rr = ty + i*8;
        t[rr][tx] = W[(long)(r0+rr)*Cv + c0+tx] * s;
    }
    __syncthreads();
#pragma unroll
    for (int i = 0; i < 4; i++) {
        int rr = ty + i*8;
        bf16 h, l;
        split2(t[rr][tx], h, l);
        XH[mo + (long)(r0+rr)*Cv + c0+tx] = h;
        XL[mo + (long)(r0+rr)*Cv + c0+tx] = l;
        split2(t[tx][rr], h, l);
        XtH[mo + (long)(c0+rr)*Cv + r0+tx] = h;
        XtL[mo + (long)(c0+rr)*Cv + r0+tx] = l;
    }
}

// ---------------- host ----------------
static inline GA mkga(const bf16* Ah, const bf16* Al, const bf16* Bh, const bf16* Bl,
                      int M, int N, int K, int lda, int ldb, long zA = 0, long zB = 0)
{
    GA g; g.Ah=Ah; g.Al=Al; g.Ah2=Ah; g.Al2=Al; g.Bh=Bh; g.Bl=Bl;
    g.M=M; g.N=N; g.K=K; g.K1=K; g.lda=lda; g.ldb=ldb; g.mskip=0; g.zA=zA; g.zB=zB;
    return g;
}
static inline TEpi te()
{
    TEpi e; e.alpha=1.f; e.beta=1.f; e.diag=0.f; e.add=0; e.zAdd=0;
    e.gelu=0; e.outF=0; e.outH=0; e.outL=0; e.zOut=0;
    return e;
}

#define SM128 (3*4*128*64)                   // 98304: 128x128 tiles, 3 stages

extern "C" void kernel_launch(void* const* d_in, const int* in_sizes, int n_in,
                              void* d_out, int out_size)
{
    const float* x   = (const float*)d_in[0];
    const float* ln1 = (const float*)d_in[1];
    const float* Wq  = (const float*)d_in[2];
    const float* Wv  = (const float*)d_in[3];
    const float* Wo  = (const float*)d_in[4];
    // d_in[5] = identity : mathematically unused (rows computed from it are discarded)
    const float* Wp1 = (const float*)d_in[6];
    const float* Wp2 = (const float*)d_in[7];
    const float* ln2 = (const float*)d_in[8];
    const float* Wfc = (const float*)d_in[9];
    const float* Wpr = (const float*)d_in[10];
    float* out = (float*)d_out;

    cudaFuncSetAttribute(mma_gemm<128,128,2,2,3>, cudaFuncAttributeMaxDynamicSharedMemorySize, SM128);

    static cudaStream_t sP = 0, sM = 0;
    static cudaEvent_t evF = 0, evJ = 0, evM = 0;
    if (!sP) {
        cudaStreamCreateWithFlags(&sP, cudaStreamNonBlocking);
        cudaStreamCreateWithFlags(&sM, cudaStreamNonBlocking);
        cudaEventCreateWithFlags(&evF, cudaEventDisableTiming);
        cudaEventCreateWithFlags(&evJ, cudaEventDisableTiming);
        cudaEventCreateWithFlags(&evM, cudaEventDisableTiming);
    }

    bf16 *qH,*qL,*vH,*vL,*hH,*hL,*fcH,*fcL;
    bf16 *WqH,*WqL,*WvH,*WvL,*WoH,*WoL,*WfcH,*WfcL,*WprH,*WprL;
    bf16 *XaH,*XaL,*XbH,*XbL,*XtH,*XtL,*YH,*YL,*MH,*ML,*PcH,*PcL;
    float *z,*YF,*part,*rn;
    cudaGetSymbolAddress((void**)&qH, g_qH);   cudaGetSymbolAddress((void**)&qL, g_qL);
    cudaGetSymbolAddress((void**)&vH, g_vH);   cudaGetSymbolAddress((void**)&vL, g_vL);
    cudaGetSymbolAddress((void**)&z,  g_z);
    cudaGetSymbolAddress((void**)&hH, g_hH);   cudaGetSymbolAddress((void**)&hL, g_hL);
    cudaGetSymbolAddress((void**)&fcH, g_fcH); cudaGetSymbolAddress((void**)&fcL, g_fcL);
    cudaGetSymbolAddress((void**)&WqH, g_WqH); cudaGetSymbolAddress((void**)&WqL, g_WqL);
    cudaGetSymbolAddress((void**)&WvH, g_WvH); cudaGetSymbolAddress((void**)&WvL, g_WvL);
    cudaGetSymbolAddress((void**)&WoH, g_WoH); cudaGetSymbolAddress((void**)&WoL, g_WoL);
    cudaGetSymbolAddress((void**)&WfcH,g_WfcH); cudaGetSymbolAddress((void**)&WfcL,g_WfcL);
    cudaGetSymbolAddress((void**)&WprH,g_WprH); cudaGetSymbolAddress((void**)&WprL,g_WprL);
    cudaGetSymbolAddress((void**)&XaH, g_XaH); cudaGetSymbolAddress((void**)&XaL, g_XaL);
    cudaGetSymbolAddress((void**)&XbH, g_XbH); cudaGetSymbolAddress((void**)&XbL, g_XbL);
    cudaGetSymbolAddress((void**)&XtH, g_XtH); cudaGetSymbolAddress((void**)&XtL, g_XtL);
    cudaGetSymbolAddress((void**)&YH,  g_YH);  cudaGetSymbolAddress((void**)&YL,  g_YL);
    cudaGetSymbolAddress((void**)&MH,  g_MH);  cudaGetSymbolAddress((void**)&ML,  g_ML);
    cudaGetSymbolAddress((void**)&PcH, g_PcH); cudaGetSymbolAddress((void**)&PcL, g_PcL);
    cudaGetSymbolAddress((void**)&YF,  g_YF);
    cudaGetSymbolAddress((void**)&part,g_part);
    cudaGetSymbolAddress((void**)&rn,  g_rn);

    // ---- fork ----
    cudaEventRecord(evF, 0);
    cudaStreamWaitEvent(sP, evF, 0);
    cudaStreamWaitEvent(sM, evF, 0);

    {   // polar chain (stream sP): 3 small launches + ONE persistent fused kernel
        frob1<<<dim3(Cv,2),128,0,sP>>>(Wp1, Wp2, part);
        frob2<<<2,256,0,sP>>>(part, rn);
        split_tr_init<<<dim3(16,16,2),dim3(32,8),0,sP>>>(Wp1, Wp2, rn, XaH, XaL, XtH, XtL);
        polar_chain<<<128,256,0,sP>>>(XaH, XaL, XbH, XbL, XtH, XtL,
                                      YH, YL, MH, ML, YF, PcH, PcL);
        cudaEventRecord(evJ, sP);
    }

    {   // main prep: weight splits + ln + q/v GEMMs (stream sM, concurrent w/ polar)
        wsplit5<<<(11*Cv*Cv)/256,256,0,sM>>>(Wq, Wv, Wo, Wfc, Wpr,
            WqH, WqL, WvH, WvL, WoH, WoL, WfcH, WfcL, WprH, WprL);
        ln_kernel<<<Rv,128,0,sM>>>(x, ln1, hH, hL);
        GA gq = mkga(hH, hL, WqH, WqL, Rv, Cv, Cv, Cv, Cv);
        TEpi eq = te(); eq.outH = qH + GUARDE; eq.outL = qL + GUARDE;
        mma_gemm<128,128,2,2,3><<<dim3(Cv/128, Rv/128), 256, SM128, sM>>>(gq, eq);
        GA gv = mkga(hH, hL, WvH, WvL, Rv, Cv, Cv, Cv, Cv);
        TEpi ev = te(); ev.outH = vH; ev.outL = vL;
        mma_gemm<128,128,2,2,3><<<dim3(Cv/128, Rv/128), 256, SM128, sM>>>(gv, ev);
        cudaEventRecord(evM, sM);
    }

    // ---- join: scan needs Pc (sP) and q (sM) ----
    cudaStreamWaitEvent(0, evJ, 0);
    cudaStreamWaitEvent(0, evM, 0);

    for (int d = 1; d < Tv; d <<= 1) {
        const int mskip = d & ~127;
        // z = qshift @ P1^T + q @ P2^T : single GEMM, K=1024
        GA gs = mkga(qH + GUARDE, qL + GUARDE, PcH, PcL, Rv, Cv, 2*Cv, Cv, 2*Cv);
        gs.Ah = qH + GUARDE - (long)d*Cv;
        gs.Al = qL + GUARDE - (long)d*Cv;
        gs.K1 = Cv;
        gs.mskip = mskip;
        gs.zA = (long)Tv*Cv;
        TEpi es = te(); es.outF = z; es.zOut = (long)Tv*Cv;
        mma_gemm<128,128,2,2,3><<<dim3(Cv/128, (Tv-mskip)/128, Bv), 256, SM128>>>(gs, es);
        pscan_combine<<<dim3((Tv-mskip)/4, Bv),512>>>(z, qH + GUARDE, qL + GUARDE, d, mskip);
    }

    // x1 = x + (q*v) @ Wo^T   (into d_out)
    mul_split<<<(Rv*Cv/4)/256,256>>>(qH + GUARDE, qL + GUARDE, vH, vL, hH, hL);
    {
        GA go = mkga(hH, hL, WoH, WoL, Rv, Cv, Cv, Cv, Cv);
        TEpi er = te(); er.add = x; er.outF = out;
        mma_gemm<128,128,2,2,3><<<dim3(Cv/128, Rv/128), 256, SM128>>>(go, er);
    }

    // ---- MLP branch ----
    ln_kernel<<<Rv,128>>>(out, ln2, hH, hL);
    {
        GA gf = mkga(hH, hL, WfcH, WfcL, Rv, Fv, Cv, Cv, Cv);
        TEpi eg = te(); eg.gelu = 1; eg.outH = fcH; eg.outL = fcL;
        mma_gemm<128,128,2,2,3><<<dim3(Fv/128, Rv/128), 256, SM128>>>(gf, eg);
        GA gr = mkga(fcH, fcL, WprH, WprL, Rv, Cv, Fv, Fv, Fv);
        TEpi er2 = te(); er2.add = out; er2.outF = out;
        mma_gemm<128,128,2,2,3><<<dim3(Cv/128, Rv/128), 256, SM128>>>(gr, er2);
    }
}